// round 16
// baseline (speedup 1.0000x reference)
#include <cuda_runtime.h>
#include <math.h>

#define N_NODES 10000
#define N_EDGES 64000
#define RHID 64
#define SQM 5.656854249492381f
#define NB 2
#define SMEM_NODE_BYTES 9216

__device__ float g_h[N_NODES * 32];
__device__ float g_rf[N_EDGES * RHID];
__device__ float g_A3[2080 * 96];
__device__ float g_asum[N_NODES * 288];
__device__ float g_cnt[N_NODES];
__device__ __align__(16) float g_WT[25 * 32768];   /* v-quad-major [path][q1][w][4] */
__device__ __align__(16) float g_WT2[25 * 32768];  /* u-quad-major [path][q1][w][4] */
__device__ __align__(16) float g_MWT[9 * 1024];    /* combined linear, quad [u4][w][4] */

typedef unsigned long long u64t;
__device__ __forceinline__ u64t pack2(float a, float b) {
    u64t r; asm("mov.b64 %0,{%1,%2};" : "=l"(r) : "f"(a), "f"(b)); return r;
}
__device__ __forceinline__ u64t pack1(float a) { return pack2(a, a); }
__device__ __forceinline__ void unpack2(u64t p, float& a, float& b) {
    asm("mov.b64 {%0,%1},%2;" : "=f"(a), "=f"(b) : "l"(p));
}
__device__ __forceinline__ void fma2(u64t& d, u64t a, u64t b) {
    asm("fma.rn.f32x2 %0,%1,%2,%0;" : "+l"(d) : "l"(a), "l"(b));
}
__device__ __forceinline__ u64t mul2(u64t a, u64t b) {
    u64t r; asm("mul.rn.f32x2 %0,%1,%2;" : "=l"(r) : "l"(a), "l"(b)); return r;
}

#define R3f   0.57735026918962576f
#define R5f   0.44721359549995794f
#define R10f  0.31622776601683794f
#define R30f  0.18257418583505536f
#define R30x2 0.36514837167011072f
#define CNA   0.20701966780270626f
#define CNB   0.23904572186687872f
#define CNC   0.11952286093343936f

template<int N> struct IC { static constexpr int v = N; };
#define T3(i,j,k,val) f(IC<i>{}, IC<j>{}, IC<k>{}, val)

template<int C> struct CGT;
template<> struct CGT<0> { static constexpr int DK=1,IB=0,JB=0,KB=0;
  template<class F> __device__ static void terms(F f){ T3(0,0,0,1.f); } };
template<> struct CGT<1> { static constexpr int DK=3,IB=0,JB=1,KB=1;
  template<class F> __device__ static void terms(F f){
    T3(0,0,0,R3f); T3(0,1,1,R3f); T3(0,2,2,R3f); } };
template<> struct CGT<2> { static constexpr int DK=5,IB=0,JB=4,KB=4;
  template<class F> __device__ static void terms(F f){
    T3(0,0,0,R5f); T3(0,1,1,R5f); T3(0,2,2,R5f); T3(0,3,3,R5f); T3(0,4,4,R5f); } };
template<> struct CGT<3> { static constexpr int DK=3,IB=1,JB=0,KB=1;
  template<class F> __device__ static void terms(F f){
    T3(0,0,0,R3f); T3(1,0,1,R3f); T3(2,0,2,R3f); } };
template<> struct CGT<4> { static constexpr int DK=1,IB=1,JB=1,KB=0;
  template<class F> __device__ static void terms(F f){
    T3(0,0,0,R3f); T3(1,1,0,R3f); T3(2,2,0,R3f); } };
template<> struct CGT<5> { static constexpr int DK=5,IB=1,JB=1,KB=4;
  template<class F> __device__ static void terms(F f){
    T3(0,1,0,R10f); T3(1,0,0,R10f); T3(1,2,1,R10f); T3(2,1,1,R10f);
    T3(0,0,2,-R30f); T3(1,1,2,-R30f); T3(2,2,2,R30x2);
    T3(0,2,3,R10f); T3(2,0,3,R10f); T3(0,0,4,R10f); T3(1,1,4,-R10f); } };
template<> struct CGT<6> { static constexpr int DK=3,IB=1,JB=4,KB=1;
  template<class F> __device__ static void terms(F f){
    T3(0,0,1,R10f); T3(1,0,0,R10f); T3(1,1,2,R10f); T3(2,1,1,R10f);
    T3(0,2,0,-R30f); T3(1,2,1,-R30f); T3(2,2,2,R30x2);
    T3(0,3,2,R10f); T3(2,3,0,R10f); T3(0,4,0,R10f); T3(1,4,1,-R10f); } };
template<> struct CGT<7> { static constexpr int DK=5,IB=4,JB=0,KB=4;
  template<class F> __device__ static void terms(F f){
    T3(0,0,0,R5f); T3(1,0,1,R5f); T3(2,0,2,R5f); T3(3,0,3,R5f); T3(4,0,4,R5f); } };
template<> struct CGT<8> { static constexpr int DK=3,IB=4,JB=1,KB=1;
  template<class F> __device__ static void terms(F f){
    T3(0,0,1,R10f); T3(0,1,0,R10f); T3(1,1,2,R10f); T3(1,2,1,R10f);
    T3(2,0,0,-R30f); T3(2,1,1,-R30f); T3(2,2,2,R30x2);
    T3(3,0,2,R10f); T3(3,2,0,R10f); T3(4,0,0,R10f); T3(4,1,1,-R10f); } };
template<> struct CGT<9> { static constexpr int DK=1,IB=4,JB=4,KB=0;
  template<class F> __device__ static void terms(F f){
    T3(0,0,0,R5f); T3(1,1,0,R5f); T3(2,2,0,R5f); T3(3,3,0,R5f); T3(4,4,0,R5f); } };
template<> struct CGT<10> { static constexpr int DK=5,IB=4,JB=4,KB=4;
  template<class F> __device__ static void terms(F f){
    T3(0,1,3,CNA); T3(0,3,1,CNA); T3(1,0,3,CNA); T3(1,3,0,CNA); T3(3,0,1,CNA); T3(3,1,0,CNA);
    T3(0,0,2,-CNB); T3(0,2,0,-CNB); T3(2,0,0,-CNB);
    T3(1,1,2,CNC); T3(1,2,1,CNC); T3(2,1,1,CNC);
    T3(3,3,2,CNC); T3(3,2,3,CNC); T3(2,3,3,CNC);
    T3(1,1,4,-CNA); T3(1,4,1,-CNA); T3(4,1,1,-CNA);
    T3(3,3,4,CNA); T3(3,4,3,CNA); T3(4,3,3,CNA);
    T3(2,2,2,CNB);
    T3(2,4,4,-CNB); T3(4,2,4,-CNB); T3(4,4,2,-CNB); } };

__device__ __forceinline__ int mergecol(int u, int slot) {
    if (slot == 0) return u;
    if (slot < 4)  return 32 + u * 3 + (slot - 1);
    return 128 + u * 5 + (slot - 4);
}

/* ----- fused init: zero + A3 + quad W transposes + combined linears - */
__global__ void mace_init(const float* __restrict__ aw, const float* __restrict__ ab,
                          const float* __restrict__ o2w, const float* __restrict__ o3a,
                          const float* __restrict__ o3b, const float* __restrict__ lino1,
                          const float* __restrict__ mixw, const float* __restrict__ combw) {
    int idx = blockIdx.x * blockDim.x + threadIdx.x;
    if (idx < N_NODES * 288) g_asum[idx] = 0.f;
    if (idx < N_NODES)       g_cnt[idx]  = 0.f;
    if (idx < 2080 * 96) {
        int k = idx / 96, n = idx - k * 96;
        int l = n >> 5, ww = n & 31;
        const float rsd[3] = {1.f, 0.57735026918962576f, 0.44721359549995794f};
        float scale = rsd[l] * (1.f / SQM);
        float v;
        if (k < 2048) { int r = k >> 5, u = k & 31; v = aw[r * 3072 + l * 1024 + u * 32 + ww]; }
        else          { int u = k - 2048;           v = ab[l * 1024 + u * 32 + ww]; }
        g_A3[idx] = v * scale;
    }
    if (idx < 25 * 32768) {
        int a = idx >> 15, r = idx & 32767;
        int q1 = r >> 7, t = r & 127;
        int w = t >> 2, c = t & 3;
        int ao = q1 >> 3, bp2 = q1 & 7;
        const float* src = (a < 3) ? (o2w + a * 32768)
                         : (a < 14) ? (o3a + (a - 3) * 32768)
                                    : (o3b + (a - 14) * 32768);
        g_WT[idx]  = src[(ao * 32 + 4 * bp2 + c) * 32 + w];   /* quad over v */
        g_WT2[idx] = src[((4 * bp2 + c) * 32 + ao) * 32 + w]; /* quad over u */
    }
    if (idx < 9 * 1024) {
        int a = idx >> 10, r = idx & 1023;
        int order = a / 3, l = a - order * 3;
        int u4 = r >> 7, t = r & 127;
        int w = t >> 2, c = t & 3;
        int u = 4 * u4 + c;
        const float* mx = mixw + (order * 3 + l) * 1024;
        const float* cb = combw + (order * 3 + l) * 1024;
        float tmp[32];
        if (order == 0) {
            const float* l1 = lino1 + l * 1024;
            for (int s = 0; s < 32; s++) {
                float acc = 0.f;
                for (int q = 0; q < 32; q++) acc += l1[u * 32 + q] * mx[q * 32 + s];
                tmp[s] = acc;
            }
        } else {
            for (int s = 0; s < 32; s++) tmp[s] = mx[u * 32 + s];
        }
        float acc = 0.f;
        for (int s = 0; s < 32; s++) acc += tmp[s] * cb[s * 32 + w];
        float scale = (order == 0) ? (1.f / 32.f) : (1.f / SQM);
        g_MWT[idx] = acc * scale;
    }
}

/* ------------- fused front: edge MLP blocks + node-h blocks --------- */
__global__ __launch_bounds__(512) void mace_front(
    const int* __restrict__ ei, const float* __restrict__ rad, const float* __restrict__ attr,
    const float* __restrict__ w1, const float* __restrict__ b1,
    const float* __restrict__ w2, const float* __restrict__ b2,
    const float* __restrict__ w3, const float* __restrict__ b3,
    const float* __restrict__ nf, const float* __restrict__ emb) {
    __shared__ float w1s[24 * 64], w2s[64 * 64], w3s[64 * 64];
    __shared__ float b1s[64], b2s[64], b3s[64];
    __shared__ float rin[8][24], x1[8][64], x2[8][64];
    int tid = threadIdx.x;
    if (blockIdx.x >= 8000) {
        int z = (blockIdx.x - 8000) * 16 + (tid >> 5);
        int ww = tid & 31;
        const float* r = nf + z * 32;
        float s = 0.f;
#pragma unroll 8
        for (int u = 0; u < 32; u++) s += r[u] * emb[u * 32 + ww];
        g_h[z * 32 + ww] = s * (1.f / SQM);
        return;
    }
    for (int i = tid; i < 1536; i += 512) w1s[i] = w1[i];
    for (int i = tid; i < 4096; i += 512) { w2s[i] = w2[i]; w3s[i] = w3[i]; }
    if (tid < 64) { b1s[tid] = b1[tid]; b2s[tid] = b2[tid]; b3s[tid] = b3[tid]; }
    int eg = tid >> 6, t = tid & 63;
    int e = blockIdx.x * 8 + eg;
    if (t < 8)       rin[eg][t] = rad[e * 8 + t];
    else if (t < 24) rin[eg][t] = attr[e * 16 + (t - 8)];
    __syncthreads();
    float s = b1s[t];
#pragma unroll
    for (int k = 0; k < 24; k++) s += rin[eg][k] * w1s[k * 64 + t];
    s = s / (1.f + expf(-s));
    x1[eg][t] = s;
    __syncthreads();
    s = b2s[t];
#pragma unroll 8
    for (int k = 0; k < 64; k++) s += x1[eg][k] * w2s[k * 64 + t];
    s = s / (1.f + expf(-s));
    x2[eg][t] = s;
    __syncthreads();
    s = b3s[t];
#pragma unroll 8
    for (int k = 0; k < 64; k++) s += x2[eg][k] * w3s[k * 64 + t];
    g_rf[e * 64 + t] = s;
    if (t == 0) atomicAdd(&g_cnt[ei[N_EDGES + e]], 1.f);
}

/* ------------ fused edge GEMM (f32x2) + SH expand + scatter --------- */
__global__ __launch_bounds__(256) void mace_edge_gemm(
    const int* __restrict__ ei, const float* __restrict__ sh) {
    __shared__ int s_src[64], s_dst[64];
    __shared__ float s_sh[64 * 9];
    __shared__ __align__(16) float Hs2[32 * 64];
    __shared__ float RFs[64 * 64];
    __shared__ __align__(8) float At[32 * 96];
    int tid = threadIdx.x;
    int e0 = blockIdx.x * 64;
    for (int i = tid; i < 64; i += 256) { s_src[i] = ei[e0 + i]; s_dst[i] = ei[N_EDGES + e0 + i]; }
    for (int i = tid; i < 576; i += 256) s_sh[i] = sh[e0 * 9 + i];
    __syncthreads();
    for (int i = tid; i < 2048; i += 256) { int u = i >> 6, e = i & 63; Hs2[u * 64 + e] = g_h[s_src[e] * 32 + u]; }
    for (int i = tid; i < 4096; i += 256) { int e = i >> 6, r = i & 63; RFs[e * 64 + r] = g_rf[(e0 + e) * 64 + r]; }
    int tx = tid & 31, ty = tid >> 5;
    u64t acc2[4][3];
#pragma unroll
    for (int p = 0; p < 4; p++) { acc2[p][0] = 0ull; acc2[p][1] = 0ull; acc2[p][2] = 0ull; }

    for (int kc = 0; kc < 2080; kc += 32) {
        __syncthreads();
        {
            u64t* At64 = (u64t*)At;
            const u64t* A364 = (const u64t*)(g_A3 + kc * 96);
            for (int i = tid; i < 1536; i += 256) At64[i] = A364[i];
        }
        __syncthreads();
        bool bias = (kc >= 2048);
        int r = kc >> 5;
        u64t prf[4];
#pragma unroll
        for (int p = 0; p < 4; p++) {
            int e = ty * 8 + 2 * p;
            prf[p] = bias ? pack2(1.f, 1.f) : pack2(RFs[e * 64 + r], RFs[(e + 1) * 64 + r]);
        }
#pragma unroll 4
        for (int kk = 0; kk < 32; kk++) {
            u64t pa0 = pack1(At[kk * 96 + tx]);
            u64t pa1 = pack1(At[kk * 96 + 32 + tx]);
            u64t pa2 = pack1(At[kk * 96 + 64 + tx]);
            const longlong2* hrow2 = (const longlong2*)&Hs2[kk * 64 + ty * 8];
            longlong2 h01 = hrow2[0], h23 = hrow2[1];
            u64t hv[4] = {(u64t)h01.x, (u64t)h01.y, (u64t)h23.x, (u64t)h23.y};
#pragma unroll
            for (int p = 0; p < 4; p++) {
                u64t pp = mul2(prf[p], hv[p]);
                fma2(acc2[p][0], pp, pa0);
                fma2(acc2[p][1], pp, pa1);
                fma2(acc2[p][2], pp, pa2);
            }
        }
    }
    __syncthreads();
    float m[8][3];
#pragma unroll
    for (int p = 0; p < 4; p++)
#pragma unroll
        for (int c = 0; c < 3; c++) unpack2(acc2[p][c], m[2 * p][c], m[2 * p + 1][c]);
#pragma unroll
    for (int i = 0; i < 8; i++) {
        int e = ty * 8 + i;
        float* ob = &g_asum[s_dst[e] * 288];
        const float* shv = &s_sh[e * 9];
        atomicAdd(ob + tx, m[i][0] * shv[0]);
#pragma unroll
        for (int q = 0; q < 3; q++) atomicAdd(ob + 32 + tx * 3 + q, m[i][1] * shv[1 + q]);
#pragma unroll
        for (int q = 0; q < 5; q++) atomicAdd(ob + 128 + tx * 5 + q, m[i][2] * shv[4 + q]);
    }
}

/* ---- pair path: register P; quad W loads in wide branch ------------ */
template<int C, bool SWAP, int UCHUNK, bool NSPLIT, bool WIDE>
__device__ void path_pair3(const float* __restrict__ x, const float* __restrict__ y,
                           int path, float* __restrict__ out, int tid) {
    constexpr int DK = CGT<C>::DK;
    constexpr int INSLOT  = SWAP ? CGT<C>::IB : CGT<C>::JB;
    constexpr int OUTSLOT = SWAP ? CGT<C>::JB : CGT<C>::IB;
    constexpr int DIN  = (INSLOT == 0) ? 1 : ((INSLOT == 1) ? 3 : 5);
    constexpr int DOUT = (OUTSLOT == 0) ? 1 : ((OUTSLOT == 1) ? 3 : 5);
    constexpr int NBP  = NSPLIT ? 1 : NB;
    constexpr int NCH  = 4 / UCHUNK;
    int g = tid >> 5, w = tid & 31;
    const float* innb = SWAP ? x : y;
    const float* outbp = SWAP ? y : x;
    const longlong2* WbQ = (const longlong2*)(SWAP ? g_WT2 : g_WT) + path * 8192 + w;
    const u64t* Wb = (const u64t*)(SWAP ? g_WT2 : g_WT) + path * 16384 + 2 * w;
    u64t acc2[NB][DK];
#pragma unroll
    for (int n = 0; n < NB; n++)
#pragma unroll
        for (int kk = 0; kk < DK; kk++) acc2[n][kk] = 0ull;

    for (int nl = 0; nl < (NSPLIT ? NB : 1); nl++) {
#pragma unroll
        for (int ch = 0; ch < NCH; ch++) {
            int a0 = g * 4 + ch * UCHUNK;
            u64t P[NBP][UCHUNK][DIN];
#pragma unroll
            for (int nn = 0; nn < NBP; nn++)
#pragma unroll
                for (int uc = 0; uc < UCHUNK; uc++)
#pragma unroll
                    for (int jm = 0; jm < DIN; jm++) P[nn][uc][jm] = 0ull;
            if (DIN == 1 || WIDE) {
#pragma unroll 2
                for (int bq = 0; bq < 8; bq++) {
                    u64t i20[NBP][DIN], i21[NBP][DIN];
#pragma unroll
                    for (int nn = 0; nn < NBP; nn++) {
                        int node = NSPLIT ? nl : nn;
#pragma unroll
                        for (int jm = 0; jm < DIN; jm++) {
                            longlong2 t4 = *(const longlong2*)&innb[node * 288 + (INSLOT + jm) * 32 + 4 * bq];
                            i20[nn][jm] = (u64t)t4.x; i21[nn][jm] = (u64t)t4.y;
                        }
                    }
#pragma unroll
                    for (int uc = 0; uc < UCHUNK; uc++) {
                        longlong2 wq = __ldg(WbQ + ((a0 + uc) * 8 + bq) * 32);
                        u64t wv0 = (u64t)wq.x, wv1 = (u64t)wq.y;
#pragma unroll
                        for (int nn = 0; nn < NBP; nn++)
#pragma unroll
                            for (int jm = 0; jm < DIN; jm++) {
                                fma2(P[nn][uc][jm], i20[nn][jm], wv0);
                                fma2(P[nn][uc][jm], i21[nn][jm], wv1);
                            }
                    }
                }
            } else {
#pragma unroll 4
                for (int bp = 0; bp < 16; bp++) {
                    u64t in2[NBP][DIN];
#pragma unroll
                    for (int nn = 0; nn < NBP; nn++) {
                        int node = NSPLIT ? nl : nn;
#pragma unroll
                        for (int jm = 0; jm < DIN; jm++)
                            in2[nn][jm] = *(const u64t*)&innb[node * 288 + (INSLOT + jm) * 32 + 2 * bp];
                    }
#pragma unroll
                    for (int uc = 0; uc < UCHUNK; uc++) {
                        u64t wv = __ldg(Wb + (((a0 + uc) * 8 + (bp >> 1)) * 32) * 2 + (bp & 1));
#pragma unroll
                        for (int nn = 0; nn < NBP; nn++)
#pragma unroll
                            for (int jm = 0; jm < DIN; jm++)
                                fma2(P[nn][uc][jm], in2[nn][jm], wv);
                    }
                }
            }
#pragma unroll
            for (int uc = 0; uc < UCHUNK; uc++) {
                int a = a0 + uc;
                float os[NBP][DOUT];
#pragma unroll
                for (int nn = 0; nn < NBP; nn++) {
                    int node = NSPLIT ? nl : nn;
#pragma unroll
                    for (int im = 0; im < DOUT; im++)
                        os[nn][im] = outbp[node * 288 + (OUTSLOT + im) * 32 + a];
                }
                CGT<C>::terms([&](auto ti, auto tj, auto tk, float val) {
                    constexpr int OI = SWAP ? decltype(tj)::v : decltype(ti)::v;
                    constexpr int PI = SWAP ? decltype(ti)::v : decltype(tj)::v;
#pragma unroll
                    for (int nn = 0; nn < NBP; nn++) {
                        int node = NSPLIT ? nl : nn;
                        fma2(acc2[node][decltype(tk)::v], pack1(os[nn][OI] * val), P[nn][uc][PI]);
                    }
                });
            }
        }
    }
#pragma unroll
    for (int n = 0; n < NB; n++)
#pragma unroll
        for (int kk = 0; kk < DK; kk++) {
            float lo, hi;
            unpack2(acc2[n][kk], lo, hi);
            atomicAdd(&out[n * 288 + (CGT<C>::KB + kk) * 32 + w], (lo + hi) * (1.f / 32.f));
        }
}

/* ---- uvu path: per-(n,u) register Q, widened loads ------------------ */
template<int C>
__device__ void path_uvu3(const float* __restrict__ x, const float* __restrict__ Wp,
                          float* __restrict__ out, int tid) {
    constexpr int DK = CGT<C>::DK;
    constexpr int IBv = CGT<C>::IB, JBv = CGT<C>::JB;
    constexpr int DJ = (JBv == 0) ? 1 : ((JBv == 1) ? 3 : 5);
    if (tid < NB * 32) {
        int n = tid >> 5, u = tid & 31;
        const float* xb = x + n * 288;
        const longlong2* Wr = (const longlong2*)(Wp + u * 32);
        u64t Q[DJ];
#pragma unroll
        for (int jm = 0; jm < DJ; jm++) Q[jm] = 0ull;
#pragma unroll
        for (int vq = 0; vq < 8; vq++) {
            longlong2 wv2 = Wr[vq];
#pragma unroll
            for (int jm = 0; jm < DJ; jm++) {
                longlong2 xv = *(const longlong2*)&xb[(JBv + jm) * 32 + 4 * vq];
                fma2(Q[jm], (u64t)xv.x, (u64t)wv2.x);
                fma2(Q[jm], (u64t)xv.y, (u64t)wv2.y);
            }
        }
        float Qs[DJ];
#pragma unroll
        for (int jm = 0; jm < DJ; jm++) { float lo, hi; unpack2(Q[jm], lo, hi); Qs[jm] = lo + hi; }
        float accs[DK];
#pragma unroll
        for (int kk = 0; kk < DK; kk++) accs[kk] = 0.f;
        CGT<C>::terms([&](auto ti, auto tj, auto tk, float val) {
            accs[decltype(tk)::v] += val * xb[(IBv + decltype(ti)::v) * 32 + u] * Qs[decltype(tj)::v];
        });
#pragma unroll
        for (int kk = 0; kk < DK; kk++)
            atomicAdd(&out[n * 288 + (CGT<C>::KB + kk) * 32 + u], accs[kk] * (1.f / SQM));
    }
}

/* combined linear via g_MWT (quad layout; wbase = order*3) */
__device__ void lin_multi(const float* in, int wbase, float* out, bool accum, int tid) {
    for (int o = tid; o < NB * 288; o += 256) {
        int n = o / 288, idx = o - n * 288;
        int slot = idx >> 5, ww = idx & 31;
        int l = (slot == 0) ? 0 : (slot < 4 ? 1 : 2);
        const longlong2* Wl = (const longlong2*)g_MWT + (wbase + l) * 256 + ww;
        const float* ib = in + n * 288 + slot * 32;
        u64t accp = 0ull;
#pragma unroll
        for (int u4 = 0; u4 < 8; u4++) {
            longlong2 iv = *(const longlong2*)(ib + 4 * u4);
            longlong2 wq = __ldg(Wl + u4 * 32);
            fma2(accp, (u64t)iv.x, (u64t)wq.x);
            fma2(accp, (u64t)iv.y, (u64t)wq.y);
        }
        float lo, hi; unpack2(accp, lo, hi);
        float s = (lo + hi) * (1.f / SQM);
        if (accum) out[o] += s; else out[o] = s;
    }
}

/* -------------------- per-node main kernel (NB=2) ------------------- */
__global__ __launch_bounds__(256, 4) void mace_node(
    const float* __restrict__ nf, const float* __restrict__ o2u,
    const float* __restrict__ selfw, float* __restrict__ out) {
    extern __shared__ __align__(16) float smem[];
    float* sa   = smem;
    float* sbuf = sa + NB * 288;
    float* st2  = sbuf + NB * 288;
    float* smsg = st2 + NB * 288;
    int z0 = blockIdx.x * NB, tid = threadIdx.x;

    for (int o = tid; o < NB * 288; o += 256) {
        int n = o / 288, idx = o - n * 288;
        int slot = idx >> 5, u = idx & 31;
        float inv = 1.f / fmaxf(g_cnt[z0 + n], 1.f);
        sa[o] = g_asum[(z0 + n) * 288 + mergecol(u, slot)] * inv;
        sbuf[o] = 0.f;
    }
    __syncthreads();
    lin_multi(sa, 0, smsg, false, tid);
    path_pair3<1, true, 4, false, true>(sa, sa, 0, sbuf, tid);
    path_pair3<2, true, 4, false, true>(sa, sa, 1, sbuf, tid);
    path_pair3<6, true, 2, false, true>(sa, sa, 2, sbuf, tid);
    path_uvu3<0> (sa, o2u,        sbuf, tid);
    path_uvu3<4> (sa, o2u + 1024, sbuf, tid);
    path_uvu3<5> (sa, o2u + 2048, sbuf, tid);
    path_uvu3<9> (sa, o2u + 3072, sbuf, tid);
    path_uvu3<10>(sa, o2u + 4096, sbuf, tid);
    __syncthreads();
    lin_multi(sbuf, 3, smsg, true, tid);
    for (int o = tid; o < NB * 288; o += 256) st2[o] = 0.f;
    __syncthreads();
    path_pair3<0, false, 4, false, true>(sa, sa, 3,  st2, tid);
    path_pair3<1, true,  4, false, true>(sa, sa, 4,  st2, tid);
    path_pair3<2, true,  4, false, true>(sa, sa, 5,  st2, tid);
    path_pair3<3, false, 4, false, true>(sa, sa, 6,  st2, tid);
    path_pair3<4, false, 2, false, true>(sa, sa, 7,  st2, tid);
    path_pair3<5, false, 2, false, false>(sa, sa, 8,  st2, tid);
    path_pair3<6, true,  2, false, true>(sa, sa, 9,  st2, tid);
    path_pair3<7, false, 4, false, true>(sa, sa, 10, st2, tid);
    path_pair3<8, false, 2, false, true>(sa, sa, 11, st2, tid);
    path_pair3<9, false, 2, true,  true>(sa, sa, 12, st2, tid);
    path_pair3<10, false, 2, true, false>(sa, sa, 13, st2, tid);
    for (int o = tid; o < NB * 288; o += 256) sbuf[o] = 0.f;
    __syncthreads();
    path_pair3<0, false, 4, false, true>(st2, sa, 14, sbuf, tid);
    path_pair3<1, true,  4, false, true>(st2, sa, 15, sbuf, tid);
    path_pair3<2, true,  4, false, true>(st2, sa, 16, sbuf, tid);
    path_pair3<3, false, 4, false, true>(st2, sa, 17, sbuf, tid);
    path_pair3<4, false, 2, false, true>(st2, sa, 18, sbuf, tid);
    path_pair3<5, false, 2, false, false>(st2, sa, 19, sbuf, tid);
    path_pair3<6, true,  2, false, true>(st2, sa, 20, sbuf, tid);
    path_pair3<7, false, 4, false, true>(st2, sa, 21, sbuf, tid);
    path_pair3<8, false, 2, false, true>(st2, sa, 22, sbuf, tid);
    path_pair3<9, false, 2, true,  true>(st2, sa, 23, sbuf, tid);
    path_pair3<10, false, 2, true, false>(st2, sa, 24, sbuf, tid);
    __syncthreads();
    lin_multi(sbuf, 6, smsg, true, tid);
    __syncthreads();
    if (tid < NB * 32) {
        int n = tid >> 5, w = tid & 31;
        const float* r = nf + (z0 + n) * 32;
        float s = 0.f;
#pragma unroll 8
        for (int v = 0; v < 32; v++) s += r[v] * __ldg(selfw + v * 32 + w);
        smsg[n * 288 + w] += s * (1.f / SQM);
    }
    __syncthreads();
    for (int o = tid; o < NB * 288; o += 256) {
        int n = o / 288, idx = o - n * 288;
        int slot = idx >> 5, u = idx & 31;
        out[(z0 + n) * 288 + mergecol(u, slot)] = smsg[o];
    }
}

/* -------------------- launch ---------------------------------------- */
extern "C" void kernel_launch(void* const* d_in, const int* in_sizes, int n_in,
                              void* d_out, int out_size) {
    const float* nf    = (const float*)d_in[0];
    const int*   ei    = (const int*)d_in[1];
    const float* sh    = (const float*)d_in[2];
    const float* rad   = (const float*)d_in[3];
    const float* attr  = (const float*)d_in[4];
    const float* w1    = (const float*)d_in[5];
    const float* b1    = (const float*)d_in[6];
    const float* w2    = (const float*)d_in[7];
    const float* b2    = (const float*)d_in[8];
    const float* w3    = (const float*)d_in[9];
    const float* b3    = (const float*)d_in[10];
    const float* aw    = (const float*)d_in[11];
    const float* ab    = (const float*)d_in[12];
    const float* emb   = (const float*)d_in[13];
    const float* lino1 = (const float*)d_in[14];
    const float* o2w   = (const float*)d_in[15];
    const float* o2u   = (const float*)d_in[16];
    const float* o3a   = (const float*)d_in[17];
    const float* o3b   = (const float*)d_in[18];
    const float* mixw  = (const float*)d_in[19];
    const float* combw = (const float*)d_in[20];
    const float* selfw = (const float*)d_in[21];

    cudaFuncSetAttribute(mace_node, cudaFuncAttributeMaxDynamicSharedMemorySize, SMEM_NODE_BYTES);

    mace_init<<<(N_NODES * 288 + 255) / 256, 256>>>(aw, ab, o2w, o3a, o3b, lino1, mixw, combw);
    mace_front<<<8000 + 625, 512>>>(ei, rad, attr, w1, b1, w2, b2, w3, b3, nf, emb);
    mace_edge_gemm<<<N_EDGES / 64, 256>>>(ei, sh);
    mace_node<<<N_NODES / NB, 256, SMEM_NODE_BYTES>>>(nf, o2u, selfw, (float*)d_out);
}

// round 17
// speedup vs baseline: 1.0289x; 1.0289x over previous
#include <cuda_runtime.h>
#include <math.h>

#define N_NODES 10000
#define N_EDGES 64000
#define RHID 64
#define SQM 5.656854249492381f
#define NB 2
#define SMEM_NODE_BYTES 9216

__device__ float g_h[N_NODES * 32];
__device__ float g_rf[N_EDGES * RHID];
__device__ float g_A3[2080 * 96];
__device__ float g_asum[N_NODES * 288];
__device__ float g_cnt[N_NODES];
__device__ __align__(16) float g_WT[25 * 32768];
__device__ __align__(16) float g_WT2[25 * 32768];
__device__ __align__(16) float g_MWT[9 * 1024];

typedef unsigned long long u64t;
__device__ __forceinline__ u64t pack2(float a, float b) {
    u64t r; asm("mov.b64 %0,{%1,%2};" : "=l"(r) : "f"(a), "f"(b)); return r;
}
__device__ __forceinline__ u64t pack1(float a) { return pack2(a, a); }
__device__ __forceinline__ void unpack2(u64t p, float& a, float& b) {
    asm("mov.b64 {%0,%1},%2;" : "=f"(a), "=f"(b) : "l"(p));
}
__device__ __forceinline__ void fma2(u64t& d, u64t a, u64t b) {
    asm("fma.rn.f32x2 %0,%1,%2,%0;" : "+l"(d) : "l"(a), "l"(b));
}
__device__ __forceinline__ u64t mul2(u64t a, u64t b) {
    u64t r; asm("mul.rn.f32x2 %0,%1,%2;" : "=l"(r) : "l"(a), "l"(b)); return r;
}

#define R3f   0.57735026918962576f
#define R5f   0.44721359549995794f
#define R10f  0.31622776601683794f
#define R30f  0.18257418583505536f
#define R30x2 0.36514837167011072f
#define CNA   0.20701966780270626f
#define CNB   0.23904572186687872f
#define CNC   0.11952286093343936f

template<int N> struct IC { static constexpr int v = N; };
#define T3(i,j,k,val) f(IC<i>{}, IC<j>{}, IC<k>{}, val)

template<int C> struct CGT;
template<> struct CGT<0> { static constexpr int DK=1,IB=0,JB=0,KB=0;
  template<class F> __device__ static void terms(F f){ T3(0,0,0,1.f); } };
template<> struct CGT<1> { static constexpr int DK=3,IB=0,JB=1,KB=1;
  template<class F> __device__ static void terms(F f){
    T3(0,0,0,R3f); T3(0,1,1,R3f); T3(0,2,2,R3f); } };
template<> struct CGT<2> { static constexpr int DK=5,IB=0,JB=4,KB=4;
  template<class F> __device__ static void terms(F f){
    T3(0,0,0,R5f); T3(0,1,1,R5f); T3(0,2,2,R5f); T3(0,3,3,R5f); T3(0,4,4,R5f); } };
template<> struct CGT<3> { static constexpr int DK=3,IB=1,JB=0,KB=1;
  template<class F> __device__ static void terms(F f){
    T3(0,0,0,R3f); T3(1,0,1,R3f); T3(2,0,2,R3f); } };
template<> struct CGT<4> { static constexpr int DK=1,IB=1,JB=1,KB=0;
  template<class F> __device__ static void terms(F f){
    T3(0,0,0,R3f); T3(1,1,0,R3f); T3(2,2,0,R3f); } };
template<> struct CGT<5> { static constexpr int DK=5,IB=1,JB=1,KB=4;
  template<class F> __device__ static void terms(F f){
    T3(0,1,0,R10f); T3(1,0,0,R10f); T3(1,2,1,R10f); T3(2,1,1,R10f);
    T3(0,0,2,-R30f); T3(1,1,2,-R30f); T3(2,2,2,R30x2);
    T3(0,2,3,R10f); T3(2,0,3,R10f); T3(0,0,4,R10f); T3(1,1,4,-R10f); } };
template<> struct CGT<6> { static constexpr int DK=3,IB=1,JB=4,KB=1;
  template<class F> __device__ static void terms(F f){
    T3(0,0,1,R10f); T3(1,0,0,R10f); T3(1,1,2,R10f); T3(2,1,1,R10f);
    T3(0,2,0,-R30f); T3(1,2,1,-R30f); T3(2,2,2,R30x2);
    T3(0,3,2,R10f); T3(2,3,0,R10f); T3(0,4,0,R10f); T3(1,4,1,-R10f); } };
template<> struct CGT<7> { static constexpr int DK=5,IB=4,JB=0,KB=4;
  template<class F> __device__ static void terms(F f){
    T3(0,0,0,R5f); T3(1,0,1,R5f); T3(2,0,2,R5f); T3(3,0,3,R5f); T3(4,0,4,R5f); } };
template<> struct CGT<8> { static constexpr int DK=3,IB=4,JB=1,KB=1;
  template<class F> __device__ static void terms(F f){
    T3(0,0,1,R10f); T3(0,1,0,R10f); T3(1,1,2,R10f); T3(1,2,1,R10f);
    T3(2,0,0,-R30f); T3(2,1,1,-R30f); T3(2,2,2,R30x2);
    T3(3,0,2,R10f); T3(3,2,0,R10f); T3(4,0,0,R10f); T3(4,1,1,-R10f); } };
template<> struct CGT<9> { static constexpr int DK=1,IB=4,JB=4,KB=0;
  template<class F> __device__ static void terms(F f){
    T3(0,0,0,R5f); T3(1,1,0,R5f); T3(2,2,0,R5f); T3(3,3,0,R5f); T3(4,4,0,R5f); } };
template<> struct CGT<10> { static constexpr int DK=5,IB=4,JB=4,KB=4;
  template<class F> __device__ static void terms(F f){
    T3(0,1,3,CNA); T3(0,3,1,CNA); T3(1,0,3,CNA); T3(1,3,0,CNA); T3(3,0,1,CNA); T3(3,1,0,CNA);
    T3(0,0,2,-CNB); T3(0,2,0,-CNB); T3(2,0,0,-CNB);
    T3(1,1,2,CNC); T3(1,2,1,CNC); T3(2,1,1,CNC);
    T3(3,3,2,CNC); T3(3,2,3,CNC); T3(2,3,3,CNC);
    T3(1,1,4,-CNA); T3(1,4,1,-CNA); T3(4,1,1,-CNA);
    T3(3,3,4,CNA); T3(3,4,3,CNA); T3(4,3,3,CNA);
    T3(2,2,2,CNB);
    T3(2,4,4,-CNB); T3(4,2,4,-CNB); T3(4,4,2,-CNB); } };

__device__ __forceinline__ int mergecol(int u, int slot) {
    if (slot == 0) return u;
    if (slot < 4)  return 32 + u * 3 + (slot - 1);
    return 128 + u * 5 + (slot - 4);
}

/* ----- fused init: zero + A3 + W transposes + combined linears ------ */
__global__ void mace_init(const float* __restrict__ aw, const float* __restrict__ ab,
                          const float* __restrict__ o2w, const float* __restrict__ o3a,
                          const float* __restrict__ o3b, const float* __restrict__ lino1,
                          const float* __restrict__ mixw, const float* __restrict__ combw) {
    int idx = blockIdx.x * blockDim.x + threadIdx.x;
    if (idx < N_NODES * 288) g_asum[idx] = 0.f;
    if (idx < N_NODES)       g_cnt[idx]  = 0.f;
    if (idx < 2080 * 96) {
        int k = idx / 96, n = idx - k * 96;
        int l = n >> 5, ww = n & 31;
        const float rsd[3] = {1.f, 0.57735026918962576f, 0.44721359549995794f};
        float scale = rsd[l] * (1.f / SQM);
        float v;
        if (k < 2048) { int r = k >> 5, u = k & 31; v = aw[r * 3072 + l * 1024 + u * 32 + ww]; }
        else          { int u = k - 2048;           v = ab[l * 1024 + u * 32 + ww]; }
        g_A3[idx] = v * scale;
    }
    if (idx < 25 * 32768) {
        int a = idx >> 15, r = idx & 32767;
        int q2 = r >> 6, t = r & 63;
        int w = t >> 1, b = t & 1;
        const float* src = (a < 3) ? (o2w + a * 32768)
                         : (a < 14) ? (o3a + (a - 3) * 32768)
                                    : (o3b + (a - 14) * 32768);
        g_WT[idx] = src[(2 * q2 + b) * 32 + w];
        int v2 = q2 >> 4, up = q2 & 15;
        g_WT2[idx] = src[((2 * up + b) * 32 + v2) * 32 + w];
    }
    if (idx < 9 * 1024) {
        int a = idx >> 10, r = idx & 1023;
        int order = a / 3, l = a - order * 3;
        int u2 = r >> 6, t = r & 63;
        int w = t >> 1, b = t & 1;
        int u = 2 * u2 + b;
        const float* mx = mixw + (order * 3 + l) * 1024;
        const float* cb = combw + (order * 3 + l) * 1024;
        float tmp[32];
        if (order == 0) {
            const float* l1 = lino1 + l * 1024;
            for (int s = 0; s < 32; s++) {
                float acc = 0.f;
                for (int q = 0; q < 32; q++) acc += l1[u * 32 + q] * mx[q * 32 + s];
                tmp[s] = acc;
            }
        } else {
            for (int s = 0; s < 32; s++) tmp[s] = mx[u * 32 + s];
        }
        float acc = 0.f;
        for (int s = 0; s < 32; s++) acc += tmp[s] * cb[s * 32 + w];
        float scale = (order == 0) ? (1.f / 32.f) : (1.f / SQM);
        g_MWT[idx] = acc * scale;
    }
}

/* ------------- fused front: edge MLP blocks + node-h blocks --------- */
__global__ __launch_bounds__(512) void mace_front(
    const int* __restrict__ ei, const float* __restrict__ rad, const float* __restrict__ attr,
    const float* __restrict__ w1, const float* __restrict__ b1,
    const float* __restrict__ w2, const float* __restrict__ b2,
    const float* __restrict__ w3, const float* __restrict__ b3,
    const float* __restrict__ nf, const float* __restrict__ emb) {
    __shared__ float w1s[24 * 64], w2s[64 * 64], w3s[64 * 64];
    __shared__ float b1s[64], b2s[64], b3s[64];
    __shared__ float rin[8][24], x1[8][64], x2[8][64];
    int tid = threadIdx.x;
    if (blockIdx.x >= 8000) {
        int z = (blockIdx.x - 8000) * 16 + (tid >> 5);
        int ww = tid & 31;
        const float* r = nf + z * 32;
        float s = 0.f;
#pragma unroll 8
        for (int u = 0; u < 32; u++) s += r[u] * emb[u * 32 + ww];
        g_h[z * 32 + ww] = s * (1.f / SQM);
        return;
    }
    for (int i = tid; i < 1536; i += 512) w1s[i] = w1[i];
    for (int i = tid; i < 4096; i += 512) { w2s[i] = w2[i]; w3s[i] = w3[i]; }
    if (tid < 64) { b1s[tid] = b1[tid]; b2s[tid] = b2[tid]; b3s[tid] = b3[tid]; }
    int eg = tid >> 6, t = tid & 63;
    int e = blockIdx.x * 8 + eg;
    if (t < 8)       rin[eg][t] = rad[e * 8 + t];
    else if (t < 24) rin[eg][t] = attr[e * 16 + (t - 8)];
    __syncthreads();
    float s = b1s[t];
#pragma unroll
    for (int k = 0; k < 24; k++) s += rin[eg][k] * w1s[k * 64 + t];
    s = s / (1.f + expf(-s));
    x1[eg][t] = s;
    __syncthreads();
    s = b2s[t];
#pragma unroll 8
    for (int k = 0; k < 64; k++) s += x1[eg][k] * w2s[k * 64 + t];
    s = s / (1.f + expf(-s));
    x2[eg][t] = s;
    __syncthreads();
    s = b3s[t];
#pragma unroll 8
    for (int k = 0; k < 64; k++) s += x2[eg][k] * w3s[k * 64 + t];
    g_rf[e * 64 + t] = s;
    if (t == 0) atomicAdd(&g_cnt[ei[N_EDGES + e]], 1.f);
}

/* ------------ fused edge GEMM (f32x2) + SH expand + scatter --------- */
__global__ __launch_bounds__(256) void mace_edge_gemm(
    const int* __restrict__ ei, const float* __restrict__ sh) {
    __shared__ int s_src[64], s_dst[64];
    __shared__ float s_sh[64 * 9];
    __shared__ __align__(16) float Hs2[32 * 64];
    __shared__ float RFs[64 * 64];
    __shared__ __align__(8) float At[32 * 96];
    int tid = threadIdx.x;
    int e0 = blockIdx.x * 64;
    for (int i = tid; i < 64; i += 256) { s_src[i] = ei[e0 + i]; s_dst[i] = ei[N_EDGES + e0 + i]; }
    for (int i = tid; i < 576; i += 256) s_sh[i] = sh[e0 * 9 + i];
    __syncthreads();
    for (int i = tid; i < 2048; i += 256) { int u = i >> 6, e = i & 63; Hs2[u * 64 + e] = g_h[s_src[e] * 32 + u]; }
    for (int i = tid; i < 4096; i += 256) { int e = i >> 6, r = i & 63; RFs[e * 64 + r] = g_rf[(e0 + e) * 64 + r]; }
    int tx = tid & 31, ty = tid >> 5;
    u64t acc2[4][3];
#pragma unroll
    for (int p = 0; p < 4; p++) { acc2[p][0] = 0ull; acc2[p][1] = 0ull; acc2[p][2] = 0ull; }

    for (int kc = 0; kc < 2080; kc += 32) {
        __syncthreads();
        {
            u64t* At64 = (u64t*)At;
            const u64t* A364 = (const u64t*)(g_A3 + kc * 96);
            for (int i = tid; i < 1536; i += 256) At64[i] = A364[i];
        }
        __syncthreads();
        bool bias = (kc >= 2048);
        int r = kc >> 5;
        u64t prf[4];
#pragma unroll
        for (int p = 0; p < 4; p++) {
            int e = ty * 8 + 2 * p;
            prf[p] = bias ? pack2(1.f, 1.f) : pack2(RFs[e * 64 + r], RFs[(e + 1) * 64 + r]);
        }
#pragma unroll 4
        for (int kk = 0; kk < 32; kk++) {
            u64t pa0 = pack1(At[kk * 96 + tx]);
            u64t pa1 = pack1(At[kk * 96 + 32 + tx]);
            u64t pa2 = pack1(At[kk * 96 + 64 + tx]);
            const longlong2* hrow2 = (const longlong2*)&Hs2[kk * 64 + ty * 8];
            longlong2 h01 = hrow2[0], h23 = hrow2[1];
            u64t hv[4] = {(u64t)h01.x, (u64t)h01.y, (u64t)h23.x, (u64t)h23.y};
#pragma unroll
            for (int p = 0; p < 4; p++) {
                u64t pp = mul2(prf[p], hv[p]);
                fma2(acc2[p][0], pp, pa0);
                fma2(acc2[p][1], pp, pa1);
                fma2(acc2[p][2], pp, pa2);
            }
        }
    }
    __syncthreads();
    float m[8][3];
#pragma unroll
    for (int p = 0; p < 4; p++)
#pragma unroll
        for (int c = 0; c < 3; c++) unpack2(acc2[p][c], m[2 * p][c], m[2 * p + 1][c]);
#pragma unroll
    for (int i = 0; i < 8; i++) {
        int e = ty * 8 + i;
        float* ob = &g_asum[s_dst[e] * 288];
        const float* shv = &s_sh[e * 9];
        atomicAdd(ob + tx, m[i][0] * shv[0]);
#pragma unroll
        for (int q = 0; q < 3; q++) atomicAdd(ob + 32 + tx * 3 + q, m[i][1] * shv[1 + q]);
#pragma unroll
        for (int q = 0; q < 5; q++) atomicAdd(ob + 128 + tx * 5 + q, m[i][2] * shv[4 + q]);
    }
}

/* ---- pair path: register P, optional LDS.128 widened in2 (R12) ----- */
template<int C, bool SWAP, int UCHUNK, bool NSPLIT, bool WIDE>
__device__ void path_pair3(const float* __restrict__ x, const float* __restrict__ y,
                           int path, float* __restrict__ out, int tid) {
    constexpr int DK = CGT<C>::DK;
    constexpr int INSLOT  = SWAP ? CGT<C>::IB : CGT<C>::JB;
    constexpr int OUTSLOT = SWAP ? CGT<C>::JB : CGT<C>::IB;
    constexpr int DIN  = (INSLOT == 0) ? 1 : ((INSLOT == 1) ? 3 : 5);
    constexpr int DOUT = (OUTSLOT == 0) ? 1 : ((OUTSLOT == 1) ? 3 : 5);
    constexpr int NBP  = NSPLIT ? 1 : NB;
    constexpr int NCH  = 4 / UCHUNK;
    int g = tid >> 5, w = tid & 31;
    const float* innb = SWAP ? x : y;
    const float* outbp = SWAP ? y : x;
    const u64t* Wb = (const u64t*)(SWAP ? g_WT2 : g_WT) + path * 16384 + w;
    u64t acc2[NB][DK];
#pragma unroll
    for (int n = 0; n < NB; n++)
#pragma unroll
        for (int kk = 0; kk < DK; kk++) acc2[n][kk] = 0ull;

    for (int nl = 0; nl < (NSPLIT ? NB : 1); nl++) {
#pragma unroll
        for (int ch = 0; ch < NCH; ch++) {
            int a0 = g * 4 + ch * UCHUNK;
            u64t P[NBP][UCHUNK][DIN];
#pragma unroll
            for (int nn = 0; nn < NBP; nn++)
#pragma unroll
                for (int uc = 0; uc < UCHUNK; uc++)
#pragma unroll
                    for (int jm = 0; jm < DIN; jm++) P[nn][uc][jm] = 0ull;
            if (DIN == 1 || WIDE) {
#pragma unroll 2
                for (int bq = 0; bq < 8; bq++) {
                    u64t i20[NBP][DIN], i21[NBP][DIN];
#pragma unroll
                    for (int nn = 0; nn < NBP; nn++) {
                        int node = NSPLIT ? nl : nn;
#pragma unroll
                        for (int jm = 0; jm < DIN; jm++) {
                            longlong2 t4 = *(const longlong2*)&innb[node * 288 + (INSLOT + jm) * 32 + 4 * bq];
                            i20[nn][jm] = (u64t)t4.x; i21[nn][jm] = (u64t)t4.y;
                        }
                    }
#pragma unroll
                    for (int uc = 0; uc < UCHUNK; uc++) {
                        u64t wv0 = __ldg(Wb + ((a0 + uc) * 16 + 2 * bq) * 32);
                        u64t wv1 = __ldg(Wb + ((a0 + uc) * 16 + 2 * bq + 1) * 32);
#pragma unroll
                        for (int nn = 0; nn < NBP; nn++)
#pragma unroll
                            for (int jm = 0; jm < DIN; jm++) {
                                fma2(P[nn][uc][jm], i20[nn][jm], wv0);
                                fma2(P[nn][uc][jm], i21[nn][jm], wv1);
                            }
                    }
                }
            } else {
#pragma unroll 4
                for (int bp = 0; bp < 16; bp++) {
                    u64t in2[NBP][DIN];
#pragma unroll
                    for (int nn = 0; nn < NBP; nn++) {
                        int node = NSPLIT ? nl : nn;
#pragma unroll
                        for (int jm = 0; jm < DIN; jm++)
                            in2[nn][jm] = *(const u64t*)&innb[node * 288 + (INSLOT + jm) * 32 + 2 * bp];
                    }
#pragma unroll
                    for (int uc = 0; uc < UCHUNK; uc++) {
                        u64t wv = __ldg(Wb + ((a0 + uc) * 16 + bp) * 32);
#pragma unroll
                        for (int nn = 0; nn < NBP; nn++)
#pragma unroll
                            for (int jm = 0; jm < DIN; jm++)
                                fma2(P[nn][uc][jm], in2[nn][jm], wv);
                    }
                }
            }
#pragma unroll
            for (int uc = 0; uc < UCHUNK; uc++) {
                int a = a0 + uc;
                float os[NBP][DOUT];
#pragma unroll
                for (int nn = 0; nn < NBP; nn++) {
                    int node = NSPLIT ? nl : nn;
#pragma unroll
                    for (int im = 0; im < DOUT; im++)
                        os[nn][im] = outbp[node * 288 + (OUTSLOT + im) * 32 + a];
                }
                CGT<C>::terms([&](auto ti, auto tj, auto tk, float val) {
                    constexpr int OI = SWAP ? decltype(tj)::v : decltype(ti)::v;
                    constexpr int PI = SWAP ? decltype(ti)::v : decltype(tj)::v;
#pragma unroll
                    for (int nn = 0; nn < NBP; nn++) {
                        int node = NSPLIT ? nl : nn;
                        fma2(acc2[node][decltype(tk)::v], pack1(os[nn][OI] * val), P[nn][uc][PI]);
                    }
                });
            }
        }
    }
#pragma unroll
    for (int n = 0; n < NB; n++)
#pragma unroll
        for (int kk = 0; kk < DK; kk++) {
            float lo, hi;
            unpack2(acc2[n][kk], lo, hi);
            atomicAdd(&out[n * 288 + (CGT<C>::KB + kk) * 32 + w], (lo + hi) * (1.f / 32.f));
        }
}

/* ---- uvu path: per-(n,u) register Q, widened loads ------------------ */
template<int C>
__device__ void path_uvu3(const float* __restrict__ x, const float* __restrict__ Wp,
                          float* __restrict__ out, int tid) {
    constexpr int DK = CGT<C>::DK;
    constexpr int IBv = CGT<C>::IB, JBv = CGT<C>::JB;
    constexpr int DJ = (JBv == 0) ? 1 : ((JBv == 1) ? 3 : 5);
    if (tid < NB * 32) {
        int n = tid >> 5, u = tid & 31;
        const float* xb = x + n * 288;
        const longlong2* Wr = (const longlong2*)(Wp + u * 32);
        u64t Q[DJ];
#pragma unroll
        for (int jm = 0; jm < DJ; jm++) Q[jm] = 0ull;
#pragma unroll
        for (int vq = 0; vq < 8; vq++) {
            longlong2 wv2 = Wr[vq];
#pragma unroll
            for (int jm = 0; jm < DJ; jm++) {
                longlong2 xv = *(const longlong2*)&xb[(JBv + jm) * 32 + 4 * vq];
                fma2(Q[jm], (u64t)xv.x, (u64t)wv2.x);
                fma2(Q[jm], (u64t)xv.y, (u64t)wv2.y);
            }
        }
        float Qs[DJ];
#pragma unroll
        for (int jm = 0; jm < DJ; jm++) { float lo, hi; unpack2(Q[jm], lo, hi); Qs[jm] = lo + hi; }
        float accs[DK];
#pragma unroll
        for (int kk = 0; kk < DK; kk++) accs[kk] = 0.f;
        CGT<C>::terms([&](auto ti, auto tj, auto tk, float val) {
            accs[decltype(tk)::v] += val * xb[(IBv + decltype(ti)::v) * 32 + u] * Qs[decltype(tj)::v];
        });
#pragma unroll
        for (int kk = 0; kk < DK; kk++)
            atomicAdd(&out[n * 288 + (CGT<C>::KB + kk) * 32 + u], accs[kk] * (1.f / SQM));
    }
}

/* combined linear via g_MWT (wbase = order*3) */
__device__ void lin_multi(const float* in, int wbase, float* out, bool accum, int tid) {
    for (int o = tid; o < NB * 288; o += 256) {
        int n = o / 288, idx = o - n * 288;
        int slot = idx >> 5, ww = idx & 31;
        int l = (slot == 0) ? 0 : (slot < 4 ? 1 : 2);
        const u64t* Wl = (const u64t*)g_MWT + (wbase + l) * 512 + ww;
        const float* ib = in + n * 288 + slot * 32;
        u64t accp = 0ull;
#pragma unroll
        for (int u4 = 0; u4 < 8; u4++) {
            longlong2 iv = *(const longlong2*)(ib + 4 * u4);
            fma2(accp, (u64t)iv.x, __ldg(Wl + (2 * u4) * 32));
            fma2(accp, (u64t)iv.y, __ldg(Wl + (2 * u4 + 1) * 32));
        }
        float lo, hi; unpack2(accp, lo, hi);
        float s = (lo + hi) * (1.f / SQM);
        if (accum) out[o] += s; else out[o] = s;
    }
}

/* -------------------- per-node main kernel (NB=2) ------------------- */
__global__ __launch_bounds__(256, 4) void mace_node(
    const float* __restrict__ nf, const float* __restrict__ o2u,
    const float* __restrict__ selfw, float* __restrict__ out) {
    extern __shared__ __align__(16) float smem[];
    float* sa   = smem;
    float* sbuf = sa + NB * 288;
    float* st2  = sbuf + NB * 288;
    float* smsg = st2 + NB * 288;
    int z0 = blockIdx.x * NB, tid = threadIdx.x;

    for (int o = tid; o < NB * 288; o += 256) {
        int n = o / 288, idx = o - n * 288;
        int slot = idx >> 5, u = idx & 31;
        float inv = 1.f / fmaxf(g_cnt[z0 + n], 1.f);
        sa[o] = g_asum[(z0 + n) * 288 + mergecol(u, slot)] * inv;
        sbuf[o] = 0.f;
    }
    __syncthreads();
    lin_multi(sa, 0, smsg, false, tid);
    path_pair3<1, true, 4, false, true>(sa, sa, 0, sbuf, tid);
    path_pair3<2, true, 4, false, true>(sa, sa, 1, sbuf, tid);
    path_pair3<6, true, 2, false, true>(sa, sa, 2, sbuf, tid);
    path_uvu3<0> (sa, o2u,        sbuf, tid);
    path_uvu3<4> (sa, o2u + 1024, sbuf, tid);
    path_uvu3<5> (sa, o2u + 2048, sbuf, tid);
    path_uvu3<9> (sa, o2u + 3072, sbuf, tid);
    path_uvu3<10>(sa, o2u + 4096, sbuf, tid);
    __syncthreads();
    lin_multi(sbuf, 3, smsg, true, tid);
    for (int o = tid; o < NB * 288; o += 256) st2[o] = 0.f;
    __syncthreads();
    path_pair3<0, false, 4, false, true>(sa, sa, 3,  st2, tid);
    path_pair3<1, true,  4, false, true>(sa, sa, 4,  st2, tid);
    path_pair3<2, true,  4, false, true>(sa, sa, 5,  st2, tid);
    path_pair3<3, false, 4, false, true>(sa, sa, 6,  st2, tid);
    path_pair3<4, false, 2, false, true>(sa, sa, 7,  st2, tid);
    path_pair3<5, false, 2, false, false>(sa, sa, 8,  st2, tid);
    path_pair3<6, true,  2, false, true>(sa, sa, 9,  st2, tid);
    path_pair3<7, false, 4, false, true>(sa, sa, 10, st2, tid);
    path_pair3<8, false, 2, false, true>(sa, sa, 11, st2, tid);
    path_pair3<9, false, 2, true,  true>(sa, sa, 12, st2, tid);
    path_pair3<10, false, 2, true, false>(sa, sa, 13, st2, tid);
    for (int o = tid; o < NB * 288; o += 256) sbuf[o] = 0.f;
    __syncthreads();
    path_pair3<0, false, 4, false, true>(st2, sa, 14, sbuf, tid);
    path_pair3<1, true,  4, false, true>(st2, sa, 15, sbuf, tid);
    path_pair3<2, true,  4, false, true>(st2, sa, 16, sbuf, tid);
    path_pair3<3, false, 4, false, true>(st2, sa, 17, sbuf, tid);
    path_pair3<4, false, 2, false, true>(st2, sa, 18, sbuf, tid);
    path_pair3<5, false, 2, false, false>(st2, sa, 19, sbuf, tid);
    path_pair3<6, true,  2, false, true>(st2, sa, 20, sbuf, tid);
    path_pair3<7, false, 4, false, true>(st2, sa, 21, sbuf, tid);
    path_pair3<8, false, 2, false, true>(st2, sa, 22, sbuf, tid);
    path_pair3<9, false, 2, true,  true>(st2, sa, 23, sbuf, tid);
    path_pair3<10, false, 2, true, false>(st2, sa, 24, sbuf, tid);
    __syncthreads();
    lin_multi(sbuf, 6, smsg, true, tid);
    __syncthreads();
    if (tid < NB * 32) {
        int n = tid >> 5, w = tid & 31;
        const float* r = nf + (z0 + n) * 32;
        float s = 0.f;
#pragma unroll 8
        for (int v = 0; v < 32; v++) s += r[v] * __ldg(selfw + v * 32 + w);
        smsg[n * 288 + w] += s * (1.f / SQM);
    }
    __syncthreads();
    for (int o = tid; o < NB * 288; o += 256) {
        int n = o / 288, idx = o - n * 288;
        int slot = idx >> 5, u = idx & 31;
        out[(z0 + n) * 288 + mergecol(u, slot)] = smsg[o];
    }
}

/* -------------------- launch ---------------------------------------- */
extern "C" void kernel_launch(void* const* d_in, const int* in_sizes, int n_in,
                              void* d_out, int out_size) {
    const float* nf    = (const float*)d_in[0];
    const int*   ei    = (const int*)d_in[1];
    const float* sh    = (const float*)d_in[2];
    const float* rad   = (const float*)d_in[3];
    const float* attr  = (const float*)d_in[4];
    const float* w1    = (const float*)d_in[5];
    const float* b1    = (const float*)d_in[6];
    const float* w2    = (const float*)d_in[7];
    const float* b2    = (const float*)d_in[8];
    const float* w3    = (const float*)d_in[9];
    const float* b3    = (const float*)d_in[10];
    const float* aw    = (const float*)d_in[11];
    const float* ab    = (const float*)d_in[12];
    const float* emb   = (const float*)d_in[13];
    const float* lino1 = (const float*)d_in[14];
    const float* o2w   = (const float*)d_in[15];
    const float* o2u   = (const float*)d_in[16];
    const float* o3a   = (const float*)d_in[17];
    const float* o3b   = (const float*)d_in[18];
    const float* mixw  = (const float*)d_in[19];
    const float* combw = (const float*)d_in[20];
    const float* selfw = (const float*)d_in[21];

    cudaFuncSetAttribute(mace_node, cudaFuncAttributeMaxDynamicSharedMemorySize, SMEM_NODE_BYTES);

    mace_init<<<(N_NODES * 288 + 255) / 256, 256>>>(aw, ab, o2w, o3a, o3b, lino1, mixw, combw);
    mace_front<<<8000 + 625, 512>>>(ei, rad, attr, w1, b1, w2, b2, w3, b3, nf, emb);
    mace_edge_gemm<<<N_EDGES / 64, 256>>>(ei, sh);
    mace_node<<<N_NODES / NB, 256, SMEM_NODE_BYTES>>>(nf, o2u, selfw, (float*)d_out);
}